// round 14
// baseline (speedup 1.0000x reference)
#include <cuda_runtime.h>
#include <cuda_fp16.h>
#include <math.h>
#include <stdint.h>

#define D_   1024
#define T_   256
#define B_   8
#define M_   (B_*T_)        // 2048 rows (b,t)
#define HMHA 16
#define DH   64
#define HGAT 8
#define GDH  128
#define KW   7
#define K5D  (5*D_)
#define KCONV (KW*D_)       // 7168

// K64 pipeline geometry (dense)
#define RB64  144                    // 64 fp16 = 128B + 16 pad
#define TB64  (128*RB64)             // 18432 B per 128-row tile
#define SMEM_K64 (2*2*TB64)          // 2 stages x 2 tiles = 73728

// Conv M256 geometry
#define TA256 (256*RB64)             // 36864 B (A tile, 256 rows)
#define CVSTG (TA256 + TB64)         // 55296 per stage
#define SMEM_C256 (2*CVSTG)          // 110592

// GAT K64 geometry (dynamic smem)
#define GA_OFF  0                    // alpha tile 128 x 64 fp16 (pitch RB64)
#define GB_OFF  TB64                 // B stages: 2 x TB64
#define GRED_OFF (GB_OFF + 2*TB64)   // 55296: e1[128], mr[128], dpart[256]
#define GSM_TOT (GRED_OFF + 2048)    // 57344

// Flash attention smem offsets
#define FQ_OFF   0
#define FK_OFF   (128*RB64)                 // 18432
#define FV_OFF   (FK_OFF + 256*RB64)        // 55296
#define FP_OFF   (FV_OFF + 64*528)          // 89088
#define FRED_OFF (FP_OFF + 128*528)         // 156672
#define FSM_TOT  (FRED_OFF + 4096)          // 160768

// ===================== PTX helpers (baseline ISA only) =====================
__device__ __forceinline__ uint32_t smem_u32(const void* p) {
    uint32_t a;
    asm("{ .reg .u64 t; cvta.to.shared.u64 t, %1; cvt.u32.u64 %0, t; }"
        : "=r"(a) : "l"(p));
    return a;
}
#define CP16(dst, src, sz) \
    asm volatile("cp.async.cg.shared.global [%0], [%1], 16, %2;" \
                 :: "r"(dst), "l"(src), "r"(sz))
#define CP_COMMIT() asm volatile("cp.async.commit_group;" ::: "memory")
#define CP_WAIT1()  asm volatile("cp.async.wait_group 1;" ::: "memory")
#define CP_WAIT0()  asm volatile("cp.async.wait_group 0;" ::: "memory")

#define LDMX4(r, addr) \
    asm volatile("ldmatrix.sync.aligned.m8n8.x4.shared.b16 {%0,%1,%2,%3}, [%4];" \
        : "=r"((r)[0]), "=r"((r)[1]), "=r"((r)[2]), "=r"((r)[3]) : "r"(addr))
#define LDMX2(r, addr) \
    asm volatile("ldmatrix.sync.aligned.m8n8.x2.shared.b16 {%0,%1}, [%2];" \
        : "=r"((r)[0]), "=r"((r)[1]) : "r"(addr))

#define MMA16816F(c, a, b) \
    asm volatile("mma.sync.aligned.m16n8k16.row.col.f32.f16.f16.f32 " \
        "{%0,%1,%2,%3}, {%4,%5,%6,%7}, {%8,%9}, {%0,%1,%2,%3};" \
        : "+f"((c)[0]), "+f"((c)[1]), "+f"((c)[2]), "+f"((c)[3]) \
        : "r"((a)[0]), "r"((a)[1]), "r"((a)[2]), "r"((a)[3]), \
          "r"((b)[0]), "r"((b)[1]))

struct Ptr5  { const float* p[5]; };
struct QkvArgs { __half* o[3]; const float* b[3]; };

// ---------------- scratch (device globals; no allocation) ----------------
__device__ __half g_f16 [M_ * D_];
__device__ __half g_wt16[5 * KW * D_ * D_];        // [c][tap][o][ci]
__device__ __half g_fp16[D_ * K5D];
__device__ __half g_dw16[5 * D_ * D_];
__device__ __half g_ms16[M_ * K5D];
__device__ float  g_z  [M_ * D_];
__device__ __half g_z16[M_ * D_];
__device__ __half g_q16[M_ * D_];
__device__ __half g_k16[M_ * D_];
__device__ __half g_v16[M_ * D_];
__device__ __half g_cx16[M_ * D_];
__device__ __half g_at16[M_ * D_];
__device__ float  g_hg [M_ * D_];
__device__ __half g_hgT[D_ * M_];
__device__ float  g_e1[M_ * HGAT];
__device__ float  g_e2[M_ * HGAT];
__device__ float  g_m2[HGAT];

// =====================================================================
// conversion kernels
// =====================================================================
__global__ __launch_bounds__(256)
void cvt_f16_kernel(const float* __restrict__ src, __half* __restrict__ hi, int n4)
{
    int i = blockIdx.x * 256 + threadIdx.x;
    if (i >= n4) return;
    float4 v = ((const float4*)src)[i];
    __half2* ph = (__half2*)hi;
    ph[2*i]   = __half2(__float2half_rn(v.x), __float2half_rn(v.y));
    ph[2*i+1] = __half2(__float2half_rn(v.z), __float2half_rn(v.w));
}

__global__ __launch_bounds__(256)
void cvt5_f16_kernel(Ptr5 ws, __half* __restrict__ hi)
{
    int c = blockIdx.y;
    int i = blockIdx.x * 256 + threadIdx.x;
    float4 v = ((const float4*)ws.p[c])[i];
    __half2* ph = (__half2*)(hi + (size_t)c * D_ * D_);
    ph[2*i]   = __half2(__float2half_rn(v.x), __float2half_rn(v.y));
    ph[2*i+1] = __half2(__float2half_rn(v.z), __float2half_rn(v.w));
}

// smem-staged conv weight transform: block = (o row, conv); coalesced both ways
__global__ __launch_bounds__(256)
void wtrans5_smem_kernel(Ptr5 cw, __half* __restrict__ wh)
{
    __shared__ float srow[KCONV];
    const int c = blockIdx.y;
    const int o = blockIdx.x;
    const int tid = threadIdx.x;
    const float4* src = (const float4*)(cw.p[c] + (size_t)o * KCONV);
    #pragma unroll
    for (int it = 0; it < 7; it++)
        ((float4*)srow)[tid + it*256] = src[tid + it*256];
    __syncthreads();
    const int ci0 = tid * 4;
    #pragma unroll
    for (int tap = 0; tap < KW; tap++) {
        float x0 = srow[(ci0+0)*7 + tap];
        float x1 = srow[(ci0+1)*7 + tap];
        float x2 = srow[(ci0+2)*7 + tap];
        float x3 = srow[(ci0+3)*7 + tap];
        __half2* dst = (__half2*)(wh + ((size_t)(c*KW + tap) << 20) + (o << 10) + ci0);
        dst[0] = __half2(__float2half_rn(x0), __float2half_rn(x1));
        dst[1] = __half2(__float2half_rn(x2), __float2half_rn(x3));
    }
}

// hg fp32 (2048 x 1024) -> hgT fp16 (1024 x 2048)
__global__ __launch_bounds__(256)
void transpose_f16_kernel(const float* __restrict__ hg, __half* __restrict__ hgT)
{
    __shared__ float tile[32][33];
    int j0 = blockIdx.x * 32, c0 = blockIdx.y * 32;
    int tx = threadIdx.x & 31, ty = threadIdx.x >> 5;
    #pragma unroll
    for (int r = ty; r < 32; r += 8)
        tile[r][tx] = hg[(size_t)(j0 + r) * D_ + c0 + tx];
    __syncthreads();
    #pragma unroll
    for (int r = ty; r < 32; r += 8)
        hgT[(size_t)(c0 + r) * M_ + j0 + tx] = __float2half_rn(tile[tx][r]);
}

// =====================================================================
// K64 fp16 1-term HMMA core (dense, 8 warps): tiles 0=A(128), 1=B(128)
// =====================================================================
__device__ __forceinline__
void hmma_chunk64(uint32_t bufu, int wm, int wn, int lane, float acc[4][4][4])
{
    #pragma unroll
    for (int kk = 0; kk < 64; kk += 16) {
        uint32_t bh[4][2];
        #pragma unroll
        for (int j = 0; j < 4; j++) {
            int nrow = wn*32 + j*8 + (lane & 7);
            int colb = (kk + ((lane >> 3) & 1)*8) * 2;
            LDMX2(bh[j], bufu + 1*TB64 + nrow*RB64 + colb);
        }
        #pragma unroll
        for (int i = 0; i < 4; i++) {
            int mrow = wm*64 + i*16 + (lane & 15);
            int colb = (kk + ((lane >> 4) & 1)*8) * 2;
            uint32_t ah[4];
            LDMX4(ah, bufu + 0*TB64 + mrow*RB64 + colb);
            #pragma unroll
            for (int j = 0; j < 4; j++)
                MMA16816F(acc[i][j], ah, bh[j]);
        }
    }
}

__device__ __forceinline__
void issue64(uint32_t smem_base, int c, int tid,
             const __half* __restrict__ A, const __half* __restrict__ W,
             int bm, int bn, int K)
{
    int k0 = c << 6;
    uint32_t bufu = smem_base + (c & 1) * 2*TB64;
    #pragma unroll
    for (int it = 0; it < 8; it++) {
        int g = tid + it*256;
        int tile = g >> 10;
        int ct = g & 1023, row = ct >> 3, cc = ct & 7;
        const __half* src = (tile == 0)
            ? A + (size_t)(bm+row)*K + k0 + cc*8
            : W + (size_t)(bn+row)*K + k0 + cc*8;
        CP16(bufu + tile*TB64 + row*RB64 + cc*16, src, 16);
    }
    CP_COMMIT();
}

__device__ __forceinline__
void epi_f32(float acc[4][4][4], const float* __restrict__ bias,
             float* __restrict__ C, int bm, int bn, int ldc,
             int wm, int wn, int lane)
{
    #pragma unroll
    for (int i = 0; i < 4; i++) {
        int m0 = bm + wm*64 + i*16 + (lane >> 2);
        #pragma unroll
        for (int j = 0; j < 4; j++) {
            int n0 = wn*32 + j*8 + (lane & 3)*2;
            float b0 = bias[bn + n0], b1 = bias[bn + n0 + 1];
            *(float2*)&C[(size_t)m0*ldc + bn + n0] =
                make_float2(acc[i][j][0] + b0, acc[i][j][1] + b1);
            *(float2*)&C[(size_t)(m0+8)*ldc + bn + n0] =
                make_float2(acc[i][j][2] + b0, acc[i][j][3] + b1);
        }
    }
}

__device__ __forceinline__
void epi_f16(float acc[4][4][4], const float* __restrict__ bias,
             __half* __restrict__ C, int bm, int bn, int ldc, int colbase,
             int wm, int wn, int lane)
{
    #pragma unroll
    for (int i = 0; i < 4; i++) {
        int m0 = bm + wm*64 + i*16 + (lane >> 2);
        #pragma unroll
        for (int j = 0; j < 4; j++) {
            int n0 = wn*32 + j*8 + (lane & 3)*2;
            float b0 = bias[bn + n0], b1 = bias[bn + n0 + 1];
            size_t o01 = (size_t)m0*ldc + colbase + bn + n0;
            size_t o23 = (size_t)(m0+8)*ldc + colbase + bn + n0;
            *(__half2*)&C[o01] = __half2(__float2half_rn(acc[i][j][0] + b0),
                                         __float2half_rn(acc[i][j][1] + b1));
            *(__half2*)&C[o23] = __half2(__float2half_rn(acc[i][j][2] + b0),
                                         __float2half_rn(acc[i][j][3] + b1));
        }
    }
}

#define HMMA_PROLOG() \
    extern __shared__ __align__(16) char smem_raw[]; \
    const uint32_t smem_base = smem_u32(smem_raw); \
    const int bm = blockIdx.y * 128, bn = blockIdx.x * 128; \
    const int tid = threadIdx.x; \
    const int wid = tid >> 5, lane = tid & 31; \
    const int wm = wid & 1, wn = wid >> 1; \
    float acc[4][4][4] = {};

#define HMMA_LOOP2(NC, ISSUE) \
    ISSUE(0); \
    for (int c = 0; c < (NC); c++) { \
        if (c + 1 < (NC)) { ISSUE(c + 1); CP_WAIT1(); } \
        else              { CP_WAIT0(); } \
        __syncthreads(); \
        hmma_chunk64(smem_base + (c & 1)*2*TB64, wm, wn, lane, acc); \
        __syncthreads(); \
    }

// ---- dense 1-term, fp32 out (fusion, gat_w) ----
__global__ __launch_bounds__(256, 2)
void hmma_1t_f32(const __half* __restrict__ A, const __half* __restrict__ W,
                 const float* __restrict__ bias, float* __restrict__ C,
                 int K, int ldc)
{
    HMMA_PROLOG();
#define ISS(c) issue64(smem_base, c, tid, A, W, bm, bn, K)
    HMMA_LOOP2(K >> 6, ISS);
#undef ISS
    epi_f32(acc, bias, C, bm, bn, ldc, wm, wn, lane);
}

// ---- dense 1-term, fp16 out (wo) ----
__global__ __launch_bounds__(256, 2)
void hmma_1t_f16(const __half* __restrict__ A, const __half* __restrict__ W,
                 const float* __restrict__ bias, __half* __restrict__ C,
                 int K, int ldc)
{
    HMMA_PROLOG();
#define ISS(c) issue64(smem_base, c, tid, A, W, bm, bn, K)
    HMMA_LOOP2(K >> 6, ISS);
#undef ISS
    epi_f16(acc, bias, C, bm, bn, ldc, 0, wm, wn, lane);
}

// ---- QKV: grid.z selects weight/bias/output, fp16 out ----
__global__ __launch_bounds__(256, 2)
void hmma_1t_qkv(const __half* __restrict__ A, const __half* __restrict__ dw16,
                 QkvArgs args)
{
    const int z = blockIdx.z;
    const __half* Wh = dw16 + (size_t)z * D_ * D_;
    HMMA_PROLOG();
#define ISS(c) issue64(smem_base, c, tid, A, Wh, bm, bn, D_)
    HMMA_LOOP2(D_ >> 6, ISS);
#undef ISS
    epi_f16(acc, args.b[z], args.o[z], bm, bn, D_, 0, wm, wn, lane);
}

// =====================================================================
// convs: M256 tile, 512 threads (16 warps of 64x32), occupancy 1.
// grid (8 n, 8 m, 5 convs). Halves weight L2 traffic vs M128.
// =====================================================================
__global__ __launch_bounds__(512, 1)
void hmma_conv256_kernel(const __half* __restrict__ Fh,
                         const __half* __restrict__ wt16, Ptr5 cbs,
                         __half* __restrict__ ms16)
{
    extern __shared__ __align__(16) char smem_raw[];
    const uint32_t smem_base = smem_u32(smem_raw);
    const int z = blockIdx.z;
    const int dil = 1 << z;
    const int ccol = z * D_;
    const __half* Wh = wt16 + (size_t)z * (KW*D_*D_);
    const int bm = blockIdx.y * 256, bn = blockIdx.x * 128;
    const int tid = threadIdx.x;
    const int wid = tid >> 5, lane = tid & 31;
    const int wm = wid & 3, wn = wid >> 2;     // 4 m-slices x 4 n-slices
    float acc[4][4][4] = {};

#define ISSUE_C2(c) do { \
    int k0 = (c) << 6; \
    int tap = k0 >> 10, ci0 = k0 & 1023; \
    int offt = (tap - 3) * dil; \
    uint32_t bufu = smem_base + ((c) & 1) * CVSTG; \
    _Pragma("unroll") \
    for (int it = 0; it < 6; it++) { \
        int g = tid + it*512; \
        if (g < 2048) { \
            int row = g >> 3, cc = g & 7; \
            int m = bm + row; \
            int bb = m >> 8, tt = (m & 255) + offt; \
            const __half* src; uint32_t sz = 16; \
            if (tt >= 0 && tt < T_) \
                src = Fh + ((size_t)(bb*T_ + tt))*D_ + ci0 + cc*8; \
            else { src = Fh; sz = 0; } \
            CP16(bufu + row*RB64 + cc*16, src, sz); \
        } else { \
            int gg = g - 2048; \
            int row = gg >> 3, cc = gg & 7; \
            const __half* src = Wh + (size_t)tap*D_*D_ + (size_t)(bn+row)*D_ + ci0 + cc*8; \
            CP16(bufu + TA256 + row*RB64 + cc*16, src, 16); \
        } \
    } \
    CP_COMMIT(); } while (0)

    const int nc = KCONV >> 6;        // 112
    ISSUE_C2(0);
    for (int c = 0; c < nc; c++) {
        if (c + 1 < nc) { ISSUE_C2(c + 1); CP_WAIT1(); }
        else            { CP_WAIT0(); }
        __syncthreads();
        uint32_t bufu = smem_base + (c & 1) * CVSTG;
        #pragma unroll
        for (int kk = 0; kk < 64; kk += 16) {
            uint32_t bh[4][2];
            #pragma unroll
            for (int j = 0; j < 4; j++) {
                int nrow = wn*32 + j*8 + (lane & 7);
                int colb = (kk + ((lane >> 3) & 1)*8) * 2;
                LDMX2(bh[j], bufu + TA256 + nrow*RB64 + colb);
            }
            #pragma unroll
            for (int i = 0; i < 4; i++) {
                int mrow = wm*64 + i*16 + (lane & 15);
                int colb = (kk + ((lane >> 4) & 1)*8) * 2;
                uint32_t ah[4];
                LDMX4(ah, bufu + mrow*RB64 + colb);
                #pragma unroll
                for (int j = 0; j < 4; j++)
                    MMA16816F(acc[i][j], ah, bh[j]);
            }
        }
        __syncthreads();
    }
#undef ISSUE_C2
    epi_f16(acc, cbs.p[z], ms16, bm, bn, K5D, ccol, wm, wn, lane);
}

// =====================================================================
// LayerNorm + exact GELU: reads z fp32, writes z16 fp16.
// =====================================================================
__global__ __launch_bounds__(256)
void ln_gelu_kernel(const float* __restrict__ z, const float* __restrict__ g,
                    const float* __restrict__ b, __half* __restrict__ z16)
{
    const int row = blockIdx.x;
    const int tid = threadIdx.x;
    const float* p = z + (size_t)row * D_;
    float4 v = ((const float4*)p)[tid];
    float s  = v.x + v.y + v.z + v.w;
    float ss = v.x*v.x + v.y*v.y + v.z*v.z + v.w*v.w;
    #pragma unroll
    for (int o = 16; o; o >>= 1) {
        s  += __shfl_xor_sync(0xffffffffu, s,  o);
        ss += __shfl_xor_sync(0xffffffffu, ss, o);
    }
    __shared__ float ws[8], wss[8];
    __shared__ float mu_s, inv_s;
    int lane = tid & 31, wid = tid >> 5;
    if (lane == 0) { ws[wid] = s; wss[wid] = ss; }
    __syncthreads();
    if (tid == 0) {
        float S = 0.f, SS = 0.f;
        #pragma unroll
        for (int i = 0; i < 8; i++) { S += ws[i]; SS += wss[i]; }
        float mu = S * (1.f / D_);
        float var = SS * (1.f / D_) - mu * mu;
        mu_s = mu;
        inv_s = rsqrtf(var + 1e-5f);
    }
    __syncthreads();
    float mu = mu_s, inv = inv_s;
    float4 gg = ((const float4*)g)[tid];
    float4 bb = ((const float4*)b)[tid];
    float y[4] = { (v.x-mu)*inv*gg.x + bb.x, (v.y-mu)*inv*gg.y + bb.y,
                   (v.z-mu)*inv*gg.z + bb.z, (v.w-mu)*inv*gg.w + bb.w };
    float o[4];
    o[0] = 0.5f*y[0]*(1.f + erff(y[0]*0.70710678118654752f));
    o[1] = 0.5f*y[1]*(1.f + erff(y[1]*0.70710678118654752f));
    o[2] = 0.5f*y[2]*(1.f + erff(y[2]*0.70710678118654752f));
    o[3] = 0.5f*y[3]*(1.f + erff(y[3]*0.70710678118654752f));
    __half2* ph = (__half2*)(z16 + (size_t)row * D_);
    ph[2*tid]   = __half2(__float2half_rn(o[0]), __float2half_rn(o[1]));
    ph[2*tid+1] = __half2(__float2half_rn(o[2]), __float2half_rn(o[3]));
}

// =====================================================================
// Flash attention: one kernel per (m-tile 128, bh). smem: Q,K,V^T,P.
// =====================================================================
__global__ __launch_bounds__(256)
void attn_flash_kernel(const __half* __restrict__ q16, const __half* __restrict__ k16,
                       const __half* __restrict__ v16, __half* __restrict__ cx16)
{
    extern __shared__ __align__(16) char fsm[];
    const uint32_t base = smem_u32(fsm);
    float* pmax = (float*)(fsm + FRED_OFF);          // [4][128]
    float* psum = (float*)(fsm + FRED_OFF + 2048);   // [4][128]
    const int bh = blockIdx.y;
    const int b = bh >> 4, h = bh & 15;
    const int bm = blockIdx.x * 128;
    const int tid = threadIdx.x;
    const int wid = tid >> 5, lane = tid & 31;
    const int wm = wid & 1, wn = wid >> 1;

    #pragma unroll
    for (int it = 0; it < 4; it++) {
        int g = tid + it*256;
        int row = g >> 3, cc = g & 7;
        CP16(base + FQ_OFF + row*RB64 + cc*16,
             q16 + (size_t)(b*T_ + bm + row)*D_ + h*DH + cc*8, 16);
    }
    #pragma unroll
    for (int it = 0; it < 8; it++) {
        int g = tid + it*256;
        int row = g >> 3, cc = g & 7;
        CP16(base + FK_OFF + row*RB64 + cc*16,
             k16 + (size_t)(b*T_ + row)*D_ + h*DH + cc*8, 16);
    }
    CP_COMMIT();
    #pragma unroll
    for (int it = 0; it < 64; it++) {
        int g = tid + it*256;
        int t = g >> 6, d = g & 63;
        *(__half*)(fsm + FV_OFF + d*528 + t*2) =
            v16[(size_t)(b*T_ + t)*D_ + h*DH + d];
    }
    CP_WAIT0();
    __syncthreads();

    float acc[4][8][4] = {};
    #pragma unroll
    for (int kk = 0; kk < 64; kk += 16) {
        uint32_t bf[8][2];
        #pragma unroll
        for (int j = 0; j < 8; j++) {
            int nrow = wn*64 + j*8 + (lane & 7);
            int colb = (kk + ((lane >> 3) & 1)*8) * 2;
            LDMX2(bf[j], base + FK_OFF + nrow*RB64 + colb);
        }
        #pragma unroll
        for (int i = 0; i < 4; i++) {
            int mrow = wm*64 + i*16 + (lane & 15);
            int colb = (kk + ((lane >> 4) & 1)*8) * 2;
            uint32_t af[4];
            LDMX4(af, base + FQ_OFF + mrow*RB64 + colb);
            #pragma unroll
            for (int j = 0; j < 8; j++)
                MMA16816F(acc[i][j], af, bf[j]);
        }
    }
    #pragma unroll
    for (int i = 0; i < 4; i++)
        #pragma unroll
        for (int j = 0; j < 8; j++)
            #pragma unroll
            for (int q = 0; q < 4; q++)
                acc[i][j][q] *= 0.125f;

    #pragma unroll
    for (int i = 0; i < 4; i++) {
        float m0 = -1e30f, m1 = -1e30f;
        #pragma unroll
        for (int j = 0; j < 8; j++) {
            m0 = fmaxf(m0, fmaxf(acc[i][j][0], acc[i][j][1]));
            m1 = fmaxf(m1, fmaxf(acc[i][j][2], acc[i][j][3]));
        }
        #pragma unroll
        for (int o = 1; o < 4; o <<= 1) {
            m0 = fmaxf(m0, __shfl_xor_sync(0xffffffffu, m0, o));
            m1 = fmaxf(m1, __shfl_xor_sync(0xffffffffu, m1, o));
        }
        if ((lane & 3) == 0) {
            int r = wm*64 + i*16 + (lane >> 2);
            pmax[wn*128 + r]     = m0;
            pmax[wn*128 + r + 8] = m1;
        }
    }
    __syncthreads();
    #pragma unroll
    for (int i = 0; i < 4; i++) {
        int r0 = wm*64 + i*16 + (lane >> 2);
        float rm0 = fmaxf(fmaxf(pmax[r0], pmax[128+r0]),
                          fmaxf(pmax[256+r0], pmax[384+r0]));
        float rm1 = fmaxf(fmaxf(pmax[r0+8], pmax[128+r0+8]),
                          fmaxf(pmax[256+r0+8], pmax[384+r0+8]));
        float s0 = 0.f, s1 = 0.f;
        #pragma unroll
        for (int j = 0; j < 8; j++) {
            int col = wn*64 + j*8 + (lane & 3)*2;
            float e0 = __expf(acc[i][j][0] - rm0);
            float e1 = __expf(acc[i][j][1] - rm0);
            float e2 = __expf(acc[i][j][2] - rm1);
            float e3 = __expf(acc[i][j][3] - rm1);
            s0 += e0 + e1; s1 += e2 + e3;
            *(__half2*)(fsm + FP_OFF + r0*528 + col*2) =
                __half2(__float2half_rn(e0), __float2half_rn(e1));
            *(__half2*)(fsm + FP_OFF + (r0+8)*528 + col*2) =
                __half2(__float2half_rn(e2), __float2half_rn(e3));
        }
        #pragma unroll
        for (int o = 1; o < 4; o <<= 1) {
            s0 += __shfl_xor_sync(0xffffffffu, s0, o);
            s1 += __shfl_xor_sync(0xffffffffu, s1, o);
        }
        if ((lane & 3) == 0) {
            int r = wm*64 + i*16 + (lane >> 2);
            psum[wn*128 + r]     = s0;
            psum[wn*128 + r + 8] = s1;
        }
    }
    __syncthreads();

    float acc2[4][2][4] = {};
    #pragma unroll
    for (int kk = 0; kk < 256; kk += 16) {
        uint32_t bf[2][2];
        #pragma unroll
        for (int j = 0; j < 2; j++) {
            int nrow = wn*16 + j*8 + (lane & 7);
            int colb = (kk + ((lane >> 3) & 1)*8) * 2;
            LDMX2(bf[j], base + FV_OFF + nrow*528 + colb);
        }
        #pragma unroll
        for (int i = 0; i < 4; i++) {
            int mrow = wm*64 + i*16 + (lane & 15);
            int colb = (kk + ((lane >> 4) & 1)*8) * 2;
            uint32_t af[4];
            LDMX4(af, base + FP_OFF + mrow*528 + colb);
            #pragma unroll
            for (int j = 0; j < 2; j++)
                MMA16816F(acc2[i][j], af, bf[j]);
        }
    }
    #pragma unroll
    for (int i = 0; i < 4; i++) {
        int r0 = wm*64 + i*16 + (lane >> 2);
        float inv0 = 1.f / (psum[r0] + psum[128+r0] + psum[256+r0] + psum[384+r0]);
        float inv1 = 1.f / (psum[r0+8] + psum[128+r0+8] + psum[256+r0+8] + psum[384+r0+8]);
        #pragma unroll
        for (int j = 0; j < 2; j++) {
            int n0 = wn*16 + j*8 + (lane & 3)*2;
            size_t o01 = (size_t)(b*T_ + bm + r0)*D_ + h*DH + n0;
            size_t o23 = (size_t)(b*T_ + bm + r0 + 8)*D_ + h*DH + n0;
            *(__half2*)&cx16[o01] = __half2(__float2half_rn(acc2[i][j][0]*inv0),
                                            __float2half_rn(acc2[i][j][1]*inv0));
            *(__half2*)&cx16[o23] = __half2(__float2half_rn(acc2[i][j][2]*inv1),
                                            __float2half_rn(acc2[i][j][3]*inv1));
        }
    }
}

// =====================================================================
// GAT pieces
// =====================================================================
__global__ __launch_bounds__(256)
void e12_kernel(const float* __restrict__ hg, const float* __restrict__ a1,
                const float* __restrict__ a2, float* __restrict__ e1,
                float* __restrict__ e2)
{
    int wid  = (blockIdx.x * blockDim.x + threadIdx.x) >> 5;
    int lane = threadIdx.x & 31;
    int n = wid >> 3, h = wid & 7;
    const float* row = hg + (size_t)n * D_ + h * GDH;
    float s1 = 0.f, s2 = 0.f;
    #pragma unroll
    for (int r = 0; r < 4; r++) {
        float x = row[lane + 32*r];
        s1 += x * a1[lane + 32*r];
        s2 += x * a2[lane + 32*r];
    }
    #pragma unroll
    for (int o = 16; o; o >>= 1) {
        s1 += __shfl_xor_sync(0xffffffffu, s1, o);
        s2 += __shfl_xor_sync(0xffffffffu, s2, o);
    }
    if (lane == 0) { e1[n*HGAT + h] = s1; e2[n*HGAT + h] = s2; }
}

__global__ __launch_bounds__(256)
void e2max_kernel(const float* __restrict__ e2, float* __restrict__ m2)
{
    int h = blockIdx.x, tid = threadIdx.x;
    float m = -1e30f;
    for (int n = tid; n < M_; n += 256) m = fmaxf(m, e2[n*HGAT + h]);
    __shared__ float sm[256];
    sm[tid] = m; __syncthreads();
    for (int s = 128; s > 0; s >>= 1) {
        if (tid < s) sm[tid] = fmaxf(sm[tid], sm[tid + s]);
        __syncthreads();
    }
    if (tid == 0) m2[h] = sm[0];
}

// GAT aggregation: K64 chunks, fp16 HMMA, on-the-fly alpha + fused epilogue.
__global__ __launch_bounds__(256)
void gat_hmma_kernel(const __half* __restrict__ hgT, const float* __restrict__ e1,
                     const float* __restrict__ e2, const float* __restrict__ m2,
                     const float* __restrict__ feat, float* __restrict__ out)
{
    extern __shared__ __align__(16) char gsm[];
    const uint32_t aU = smem_u32(gsm);               // alpha tile at offset 0
    float* s_e1  = (float*)(gsm + GRED_OFF);
    float* s_mr  = (float*)(gsm + GRED_OFF + 512);
    float* dpart = (float*)(gsm + GRED_OFF + 1024);
    const int h  = blockIdx.x;
    const int bm = blockIdx.y * 128;
    const int tid = threadIdx.x;
    const int wid = tid >> 5, lane = tid & 31;
    const int wm = wid & 1, wn = wid >> 1;
    if (tid < 128) {
        float v1 = e1[(bm + tid)*HGAT + h];
        float sv = v1 + m2[h];
        s_mr[tid] = sv > 0.f ? sv : 0.2f * sv;
        s_e1[tid] = v1;
    }
    __syncthreads();
    const int am  = tid >> 1;                        // alpha row owned
    const int ak0 = (tid & 1) * 32;                  // half of the 64 k-cols
    const float e1v = s_e1[am], mrv = s_mr[am];
    float dreg = 0.f;
    float acc[4][4][4] = {};

#define ISSUE_B(c) do { \
    int k0 = (c) << 6; \
    uint32_t bufu = aU + GB_OFF + ((c) & 1) * TB64; \
    _Pragma("unroll") \
    for (int it = 0; it < 4; it++) { \
        int g = tid + it*256; \
        int row = g >> 3, cc = g & 7; \
        const __half* src = hgT + (size_t)(h*GDH + row)*M_ + k0 + cc*8; \
        CP16(bufu + row*RB64 + cc*16, src, 16); \
    } \
    CP_COMMIT(); } while (0)

    const int nc = M_ >> 6;               // 32
    ISSUE_B(0);
    for (int c = 0; c < nc; c++) {
        int k0 = c << 6;
        #pragma unroll
        for (int r = 0; r < 32; r++) {
            int j = k0 + ak0 + r;
            float ev = __ldg(&e2[j*HGAT + h]);
            float sv = e1v + ev;
            float lv = sv > 0.f ? sv : 0.2f * sv;
            __half a16 = __float2half_rn(__expf(lv - mrv));
            dreg += __half2float(a16);
            *(__half*)(gsm + am*RB64 + (ak0 + r)*2) = a16;
        }
        if (c + 1 < nc) { ISSUE_B(c + 1); CP_WAIT1(); }
        else            { CP_WAIT0(); }
        __syncthreads();
        uint32_t bU = aU + GB_OFF + (c & 1) * TB64;
        #pragma unroll
        for (int kk = 0; kk < 64; kk += 16) {
            uint32_t bhf[4][2];
            #pragma unroll
            for (int j = 0; j < 4; j++) {
                int nrow = wn*32 + j*8 + (lane & 7);
                int colb = (kk + ((lane >> 3) & 1)*8) * 2;
                LDMX2(bhf[j], bU + nrow*RB64 + colb);
            }
            #pragma unroll
            for (int i = 0; i < 4; i++) {
                int mrow = wm*64 + i*16 + (lane & 15);
                int colb = (kk + ((lane >> 4) & 1)*8) * 2;
                uint32_t ah[4];
                LDMX4(ah, aU + mrow*RB64 + colb);
                #pragma unroll
                for (int j = 0; j < 4; j++)
                    MMA16816F(acc[i][j], ah, bhf[j]);
            }
        }
        __syncthreads();
    }
#undef ISSUE_B
    dpart[tid] = dreg;
    __syncthreads();
    #pragma unroll
    for (int i = 0; i < 4; i++) {
        int ml = wm*64 + i*16 + (lane >> 2);
        int m0 = bm + ml;
        float inv0 = 1.f / (dpart[2*ml] + dpart[2*ml+1]);
        float inv1 = 1.f / (dpart[2*(ml+8)] + dpart[2*(ml+8)+1]);
        #pragma unroll
        for (int j = 0; j < 4; j++) {
            int n0 = wn*32 + j*8 + (lane & 3)*2;
            int col = h*GDH + n0;
            float v0 = acc[i][j][0]*inv0, v1 = acc[i][j][1]*inv0;
            float v2 = acc[i][j][2]*inv1, v3 = acc[i][j][3]*inv1;
            v0 = v0 > 0.f ? v0 : expm1f(v0);
            v1 = v1 > 0.f ? v1 : expm1f(v1);
            v2 = v2 > 0.f ? v2 : expm1f(v2);
            v3 = v3 > 0.f ? v3 : expm1f(v3);
            size_t o01 = (size_t)m0*D_ + col;
            size_t o23 = (size_t)(m0+8)*D_ + col;
            out[o01]   = v0 + feat[o01];
            out[o01+1] = v1 + feat[o01+1];
            out[o23]   = v2 + feat[o23];
            out[o23+1] = v3 + feat[o23+1];
        }
    }
}

// =====================================================================
extern "C" void kernel_launch(void* const* d_in, const int* in_sizes, int n_in,
                              void* d_out, int out_size)
{
    const float* feat = (const float*)d_in[0];

    Ptr5 cw{}, cb{};
    int wi = 0, bi = 0;
    for (int i = 1; i <= 10; i++) {
        if (in_sizes[i] == D_ * D_ * KW) { if (wi < 5) cw.p[wi++] = (const float*)d_in[i]; }
        else                             { if (bi < 5) cb.p[bi++] = (const float*)d_in[i]; }
    }

    const float* fp_w = (const float*)d_in[11];
    const float* fp_b = (const float*)d_in[12];
    const float* ln_g = (const float*)d_in[13];
    const float* ln_b = (const float*)d_in[14];
    const float* wq = (const float*)d_in[15];
    const float* bq = (const float*)d_in[16];
    const float* wk = (const float*)d_in[17];
    const float* bk = (const float*)d_in[18];
    const float* wv = (const float*)d_in[19];
    const float* bv = (const float*)d_in[20];
    const float* wo = (const float*)d_in[21];
    const float* bo = (const float*)d_in[22];
    const float* gat_w = (const float*)d_in[23];
    const float* gat_b = (const float*)d_in[24];
    const float* a1 = (const float*)d_in[25];
    const float* a2 = (const float*)d_in[26];
    float* out = (float*)d_out;

    __half *f16, *wt16, *fp16, *dw16, *ms16, *z16, *q16, *k16, *v16;
    __half *cx16, *at16, *hgT;
    float *z, *hg, *e1, *e2, *m2;
    cudaGetSymbolAddress((void**)&f16,  g_f16);
    cudaGetSymbolAddress((void**)&wt16, g_wt16);
    cudaGetSymbolAddress((void**)&fp16, g_fp16);
    cudaGetSymbolAddress((void**)&dw16, g_dw16);
    cudaGetSymbolAddress((void**)&ms16, g_ms16);
    cudaGetSymbolAddress((void**)&z,    g_z);
    cudaGetSymbolAddress((void**)&z16,  g_z16);
    cudaGetSymbolAddress((void**)&q16,  g_q16);
    cudaGetSymbolAddress((void**)&k16,  g_k16);
    cudaGetSymbolAddress((void**)&v16,  g_v16);
    cudaGetSymbolAddress((void**)&cx16, g_cx16);
    cudaGetSymbolAddress((void**)&at16, g_at16);
    cudaGetSymbolAddress((void**)&hg,   g_hg);
    cudaGetSymbolAddress((void**)&hgT,  g_hgT);
    cudaGetSymbolAddress((void**)&e1,   g_e1);
    cudaGetSymbolAddress((void**)&e2,   g_e2);
    cudaGetSymbolAddress((void**)&m2,   g_m2);

    cudaFuncSetAttribute(hmma_1t_f32,        cudaFuncAttributeMaxDynamicSharedMemorySize, SMEM_K64);
    cudaFuncSetAttribute(hmma_1t_f16,        cudaFuncAttributeMaxDynamicSharedMemorySize, SMEM_K64);
    cudaFuncSetAttribute(hmma_1t_qkv,        cudaFuncAttributeMaxDynamicSharedMemorySize, SMEM_K64);
    cudaFuncSetAttribute(hmma_conv256_kernel, cudaFuncAttributeMaxDynamicSharedMemorySize, SMEM_C256);
    cudaFuncSetAttribute(attn_flash_kernel,  cudaFuncAttributeMaxDynamicSharedMemorySize, FSM_TOT);
    cudaFuncSetAttribute(gat_hmma_kernel,    cudaFuncAttributeMaxDynamicSharedMemorySize, GSM_TOT);

    // 0) conversions
    cvt_f16_kernel<<<(M_*D_/4 + 255)/256, 256>>>(feat, f16, M_*D_/4);
    wtrans5_smem_kernel<<<dim3(D_, 5), 256>>>(cw, wt16);
    cvt_f16_kernel<<<(D_*K5D/4 + 255)/256, 256>>>(fp_w, fp16, D_*K5D/4);
    Ptr5 dws{{ wq, wk, wv, wo, gat_w }};
    cvt5_f16_kernel<<<dim3(D_*D_/4/256, 5), 256>>>(dws, dw16);

    // 1) dilated convs (fp16 1-term, M256/K64) -> ms16
    hmma_conv256_kernel<<<dim3(8, 8, 5), 512, SMEM_C256>>>(f16, wt16, cb, ms16);

    // 2) fusion projection (K=5120) -> z fp32, then LN+GELU -> z16
    hmma_1t_f32<<<dim3(8, 16), 256, SMEM_K64>>>(ms16, fp16, fp_b, z, K5D, D_);
    ln_gelu_kernel<<<M_, 256>>>(z, ln_g, ln_b, z16);

    // 3) q, k, v projections (merged)
    QkvArgs qkv{{ q16, k16, v16 }, { bq, bk, bv }};
    hmma_1t_qkv<<<dim3(8, 16, 3), 256, SMEM_K64>>>(z16, dw16, qkv);

    // 4) attention: single flash kernel
    attn_flash_kernel<<<dim3(2, B_*HMHA), 256, FSM_TOT>>>(q16, k16, v16, cx16);

    // 5) wo -> at16; gat_w -> hg fp32
    hmma_1t_f16<<<dim3(8, 16), 256, SMEM_K64>>>(cx16,
        dw16 + 3*(size_t)D_*D_, bo, at16, D_, D_);
    hmma_1t_f32<<<dim3(8, 16), 256, SMEM_K64>>>(at16,
        dw16 + 4*(size_t)D_*D_, gat_b, hg, D_, D_);

    // 6) GAT logits, max, transpose
    e12_kernel<<<(M_*HGAT)/8, 256>>>(hg, a1, a2, e1, e2);
    e2max_kernel<<<HGAT, 256>>>(e2, m2);
    transpose_f16_kernel<<<dim3(M_/32, D_/32), 256>>>(hg, hgT);

    // 7) GAT aggregation (fp16 HMMA, K64) + ELU + residual -> d_out
    gat_hmma_kernel<<<dim3(HGAT, 16), 256, GSM_TOT>>>(hgT, e1, e2, m2, feat, out);
}

// round 15
// speedup vs baseline: 1.1727x; 1.1727x over previous
#include <cuda_runtime.h>
#include <cuda_fp16.h>
#include <math.h>
#include <stdint.h>

#define D_   1024
#define T_   256
#define B_   8
#define M_   (B_*T_)        // 2048 rows (b,t)
#define HMHA 16
#define DH   64
#define HGAT 8
#define GDH  128
#define KW   7
#define K5D  (5*D_)
#define KCONV (KW*D_)       // 7168

// K64 pipeline geometry (dense + conv)
#define RB64  144                    // 64 fp16 = 128B + 16 pad
#define TB64  (128*RB64)             // 18432 B per 128-row tile
#define SMEM_K64 (2*2*TB64)          // 2 stages x 2 tiles = 73728

// GAT K64 geometry (dynamic smem)
#define GB_OFF  TB64                 // B stages: 2 x TB64 after alpha tile
#define GRED_OFF (GB_OFF + 2*TB64)   // 55296
#define GSM_TOT (GRED_OFF + 2048)    // 57344

// Flash attention smem offsets
#define FQ_OFF   0
#define FK_OFF   (128*RB64)                 // 18432
#define FV_OFF   (FK_OFF + 256*RB64)        // 55296
#define FP_OFF   (FV_OFF + 64*528)          // 89088
#define FRED_OFF (FP_OFF + 128*528)         // 156672
#define FSM_TOT  (FRED_OFF + 4096)          // 160768

// ===================== PTX helpers (baseline ISA only) =====================
__device__ __forceinline__ uint32_t smem_u32(const void* p) {
    uint32_t a;
    asm("{ .reg .u64 t; cvta.to.shared.u64 t, %1; cvt.u32.u64 %0, t; }"
        : "=r"(a) : "l"(p));
    return a;
}
#define CP16(dst, src, sz) \
    asm volatile("cp.async.cg.shared.global [%0], [%1], 16, %2;" \
                 :: "r"(dst), "l"(src), "r"(sz))
#define CP_COMMIT() asm volatile("cp.async.commit_group;" ::: "memory")
#define CP_WAIT1()  asm volatile("cp.async.wait_group 1;" ::: "memory")
#define CP_WAIT0()  asm volatile("cp.async.wait_group 0;" ::: "memory")

#define LDMX4(r, addr) \
    asm volatile("ldmatrix.sync.aligned.m8n8.x4.shared.b16 {%0,%1,%2,%3}, [%4];" \
        : "=r"((r)[0]), "=r"((r)[1]), "=r"((r)[2]), "=r"((r)[3]) : "r"(addr))
#define LDMX2(r, addr) \
    asm volatile("ldmatrix.sync.aligned.m8n8.x2.shared.b16 {%0,%1}, [%2];" \
        : "=r"((r)[0]), "=r"((r)[1]) : "r"(addr))

#define MMA16816F(c, a, b) \
    asm volatile("mma.sync.aligned.m16n8k16.row.col.f32.f16.f16.f32 " \
        "{%0,%1,%2,%3}, {%4,%5,%6,%7}, {%8,%9}, {%0,%1,%2,%3};" \
        : "+f"((c)[0]), "+f"((c)[1]), "+f"((c)[2]), "+f"((c)[3]) \
        : "r"((a)[0]), "r"((a)[1]), "r"((a)[2]), "r"((a)[3]), \
          "r"((b)[0]), "r"((b)[1]))

struct Ptr5  { const float* p[5]; };
struct QkvArgs { __half* o[3]; const float* b[3]; };

// ---------------- scratch (device globals; no allocation) ----------------
__device__ __half g_f16 [M_ * D_];
__device__ __half g_wt16[5 * KW * D_ * D_];        // [c][tap][o][ci]
__device__ __half g_fp16[D_ * K5D];
__device__ __half g_dw16[5 * D_ * D_];
__device__ __half g_ms16[M_ * K5D];
__device__ float  g_z  [M_ * D_];
__device__ __half g_z16[M_ * D_];
__device__ __half g_q16[M_ * D_];
__device__ __half g_k16[M_ * D_];
__device__ __half g_v16[M_ * D_];
__device__ __half g_cx16[M_ * D_];
__device__ __half g_at16[M_ * D_];
__device__ float  g_hg [M_ * D_];
__device__ __half g_hgT[D_ * M_];
__device__ float  g_e1[M_ * HGAT];
__device__ float  g_e2[M_ * HGAT];
__device__ float  g_m2[HGAT];

// =====================================================================
// conversion kernels
// =====================================================================
__global__ __launch_bounds__(256)
void cvt_f16_kernel(const float* __restrict__ src, __half* __restrict__ hi, int n4)
{
    int i = blockIdx.x * 256 + threadIdx.x;
    if (i >= n4) return;
    float4 v = ((const float4*)src)[i];
    __half2* ph = (__half2*)hi;
    ph[2*i]   = __half2(__float2half_rn(v.x), __float2half_rn(v.y));
    ph[2*i+1] = __half2(__float2half_rn(v.z), __float2half_rn(v.w));
}

__global__ __launch_bounds__(256)
void cvt5_f16_kernel(Ptr5 ws, __half* __restrict__ hi)
{
    int c = blockIdx.y;
    int i = blockIdx.x * 256 + threadIdx.x;
    float4 v = ((const float4*)ws.p[c])[i];
    __half2* ph = (__half2*)(hi + (size_t)c * D_ * D_);
    ph[2*i]   = __half2(__float2half_rn(v.x), __float2half_rn(v.y));
    ph[2*i+1] = __half2(__float2half_rn(v.z), __float2half_rn(v.w));
}

// smem-staged conv weight transform: block = (o row, conv); coalesced both ways
__global__ __launch_bounds__(256)
void wtrans5_smem_kernel(Ptr5 cw, __half* __restrict__ wh)
{
    __shared__ float srow[KCONV];
    const int c = blockIdx.y;
    const int o = blockIdx.x;
    const int tid = threadIdx.x;
    const float4* src = (const float4*)(cw.p[c] + (size_t)o * KCONV);
    #pragma unroll
    for (int it = 0; it < 7; it++)
        ((float4*)srow)[tid + it*256] = src[tid + it*256];
    __syncthreads();
    const int ci0 = tid * 4;
    #pragma unroll
    for (int tap = 0; tap < KW; tap++) {
        float x0 = srow[(ci0+0)*7 + tap];
        float x1 = srow[(ci0+1)*7 + tap];
        float x2 = srow[(ci0+2)*7 + tap];
        float x3 = srow[(ci0+3)*7 + tap];
        __half2* dst = (__half2*)(wh + ((size_t)(c*KW + tap) << 20) + (o << 10) + ci0);
        dst[0] = __half2(__float2half_rn(x0), __float2half_rn(x1));
        dst[1] = __half2(__float2half_rn(x2), __float2half_rn(x3));
    }
}

// hg fp32 (2048 x 1024) -> hgT fp16 (1024 x 2048)
__global__ __launch_bounds__(256)
void transpose_f16_kernel(const float* __restrict__ hg, __half* __restrict__ hgT)
{
    __shared__ float tile[32][33];
    int j0 = blockIdx.x * 32, c0 = blockIdx.y * 32;
    int tx = threadIdx.x & 31, ty = threadIdx.x >> 5;
    #pragma unroll
    for (int r = ty; r < 32; r += 8)
        tile[r][tx] = hg[(size_t)(j0 + r) * D_ + c0 + tx];
    __syncthreads();
    #pragma unroll
    for (int r = ty; r < 32; r += 8)
        hgT[(size_t)(c0 + r) * M_ + j0 + tx] = __float2half_rn(tile[tx][r]);
}

// =====================================================================
// K64 fp16 1-term HMMA core: tiles 0=A, 1=B  (pitch RB64)
// =====================================================================
__device__ __forceinline__
void hmma_chunk64(uint32_t bufu, int wm, int wn, int lane, float acc[4][4][4])
{
    #pragma unroll
    for (int kk = 0; kk < 64; kk += 16) {
        uint32_t bh[4][2];
        #pragma unroll
        for (int j = 0; j < 4; j++) {
            int nrow = wn*32 + j*8 + (lane & 7);
            int colb = (kk + ((lane >> 3) & 1)*8) * 2;
            LDMX2(bh[j], bufu + 1*TB64 + nrow*RB64 + colb);
        }
        #pragma unroll
        for (int i = 0; i < 4; i++) {
            int mrow = wm*64 + i*16 + (lane & 15);
            int colb = (kk + ((lane >> 4) & 1)*8) * 2;
            uint32_t ah[4];
            LDMX4(ah, bufu + 0*TB64 + mrow*RB64 + colb);
            #pragma unroll
            for (int j = 0; j < 4; j++)
                MMA16816F(acc[i][j], ah, bh[j]);
        }
    }
}

__device__ __forceinline__
void issue64(uint32_t smem_base, int c, int tid,
             const __half* __restrict__ A, const __half* __restrict__ W,
             int bm, int bn, int K)
{
    int k0 = c << 6;
    uint32_t bufu = smem_base + (c & 1) * 2*TB64;
    #pragma unroll
    for (int it = 0; it < 8; it++) {
        int g = tid + it*256;
        int tile = g >> 10;
        int ct = g & 1023, row = ct >> 3, cc = ct & 7;
        const __half* src = (tile == 0)
            ? A + (size_t)(bm+row)*K + k0 + cc*8
            : W + (size_t)(bn+row)*K + k0 + cc*8;
        CP16(bufu + tile*TB64 + row*RB64 + cc*16, src, 16);
    }
    CP_COMMIT();
}

__device__ __forceinline__
void epi_f32(float acc[4][4][4], const float* __restrict__ bias,
             float* __restrict__ C, int bm, int bn, int ldc,
             int wm, int wn, int lane)
{
    #pragma unroll
    for (int i = 0; i < 4; i++) {
        int m0 = bm + wm*64 + i*16 + (lane >> 2);
        #pragma unroll
        for (int j = 0; j < 4; j++) {
            int n0 = wn*32 + j*8 + (lane & 3)*2;
            float b0 = bias[bn + n0], b1 = bias[bn + n0 + 1];
            *(float2*)&C[(size_t)m0*ldc + bn + n0] =
                make_float2(acc[i][j][0] + b0, acc[i][j][1] + b1);
            *(float2*)&C[(size_t)(m0+8)*ldc + bn + n0] =
                make_float2(acc[i][j][2] + b0, acc[i][j][3] + b1);
        }
    }
}

__device__ __forceinline__
void epi_f16(float acc[4][4][4], const float* __restrict__ bias,
             __half* __restrict__ C, int bm, int bn, int ldc, int colbase,
             int wm, int wn, int lane)
{
    #pragma unroll
    for (int i = 0; i < 4; i++) {
        int m0 = bm + wm*64 + i*16 + (lane >> 2);
        #pragma unroll
        for (int j = 0; j < 4; j++) {
            int n0 = wn*32 + j*8 + (lane & 3)*2;
            float b0 = bias[bn + n0], b1 = bias[bn + n0 + 1];
            size_t o01 = (size_t)m0*ldc + colbase + bn + n0;
            size_t o23 = (size_t)(m0+8)*ldc + colbase + bn + n0;
            *(__half2*)&C[o01] = __half2(__float2half_rn(acc[i][j][0] + b0),
                                         __float2half_rn(acc[i][j][1] + b1));
            *(__half2*)&C[o23] = __half2(__float2half_rn(acc[i][j][2] + b0),
                                         __float2half_rn(acc[i][j][3] + b1));
        }
    }
}

#define HMMA_PROLOG() \
    extern __shared__ __align__(16) char smem_raw[]; \
    const uint32_t smem_base = smem_u32(smem_raw); \
    const int bm = blockIdx.y * 128, bn = blockIdx.x * 128; \
    const int tid = threadIdx.x; \
    const int wid = tid >> 5, lane = tid & 31; \
    const int wm = wid & 1, wn = wid >> 1; \
    float acc[4][4][4] = {};

#define HMMA_LOOP2(NC, ISSUE) \
    ISSUE(0); \
    for (int c = 0; c < (NC); c++) { \
        if (c + 1 < (NC)) { ISSUE(c + 1); CP_WAIT1(); } \
        else              { CP_WAIT0(); } \
        __syncthreads(); \
        hmma_chunk64(smem_base + (c & 1)*2*TB64, wm, wn, lane, acc); \
        __syncthreads(); \
    }

// ---- dense 1-term, fp32 out (fusion, gat_w) ----
__global__ __launch_bounds__(256, 2)
void hmma_1t_f32(const __half* __restrict__ A, const __half* __restrict__ W,
                 const float* __restrict__ bias, float* __restrict__ C,
                 int K, int ldc)
{
    HMMA_PROLOG();
#define ISS(c) issue64(smem_base, c, tid, A, W, bm, bn, K)
    HMMA_LOOP2(K >> 6, ISS);
#undef ISS
    epi_f32(acc, bias, C, bm, bn, ldc, wm, wn, lane);
}

// ---- dense 1-term, fp16 out (wo) ----
__global__ __launch_bounds__(256, 2)
void hmma_1t_f16(const __half* __restrict__ A, const __half* __restrict__ W,
                 const float* __restrict__ bias, __half* __restrict__ C,
                 int K, int ldc)
{
    HMMA_PROLOG();
#define ISS(c) issue64(smem_base, c, tid, A, W, bm, bn, K)
    HMMA_LOOP2(K >> 6, ISS);
#undef ISS
    epi_f16(acc, bias, C, bm, bn, ldc, 0, wm, wn, lane);
}

// ---- QKV: grid.z selects weight/bias/output, fp16 out ----
__global__ __launch_bounds__(256, 2)
void hmma_1t_qkv(const __half* __restrict__ A, const __half* __restrict__ dw16,
                 QkvArgs args)
{
    const int z = blockIdx.z;
    const __half* Wh = dw16 + (size_t)z * D_ * D_;
    HMMA_PROLOG();
#define ISS(c) issue64(smem_base, c, tid, A, Wh, bm, bn, D_)
    HMMA_LOOP2(D_ >> 6, ISS);
#undef ISS
    epi_f16(acc, args.b[z], args.o[z], bm, bn, D_, 0, wm, wn, lane);
}

// ---- convs: fp16 1-term gather, grid.z = conv id, fp16 out (R13 proven) ----
__global__ __launch_bounds__(256, 2)
void hmma_conv_kernel(const __half* __restrict__ Fh,
                      const __half* __restrict__ wt16, Ptr5 cbs,
                      __half* __restrict__ ms16)
{
    const int z = blockIdx.z;
    const int dil = 1 << z;
    const int ccol = z * D_;
    const __half* Wh = wt16 + (size_t)z * (KW*D_*D_);
    HMMA_PROLOG();

#define ISSUE_C(c) do { \
    int k0 = (c) << 6; \
    int tap = k0 >> 10, ci0 = k0 & 1023; \
    int offt = (tap - 3) * dil; \
    uint32_t bufu = smem_base + ((c) & 1) * 2*TB64; \
    _Pragma("unroll") \
    for (int it = 0; it < 8; it++) { \
        int g = tid + it*256; \
        int tile = g >> 10; \
        int ct = g & 1023; int row = ct >> 3, cc = ct & 7; \
        const __half* src; \
        uint32_t sz = 16; \
        if (tile == 0) { \
            int m = bm + row; \
            int bb = m >> 8, tt = (m & 255) + offt; \
            if (tt >= 0 && tt < T_) \
                src = Fh + ((size_t)(bb*T_ + tt))*D_ + ci0 + cc*8; \
            else { src = Fh; sz = 0; } \
        } else { \
            src = Wh + (size_t)tap*D_*D_ + (size_t)(bn+row)*D_ + ci0 + cc*8; \
        } \
        CP16(bufu + tile*TB64 + row*RB64 + cc*16, src, sz); \
    } \
    CP_COMMIT(); } while (0)

    HMMA_LOOP2(KCONV >> 6, ISSUE_C);
#undef ISSUE_C
    epi_f16(acc, cbs.p[z], ms16, bm, bn, K5D, ccol, wm, wn, lane);
}

// =====================================================================
// LayerNorm + exact GELU: reads z fp32, writes z16 fp16.
// =====================================================================
__global__ __launch_bounds__(256)
void ln_gelu_kernel(const float* __restrict__ z, const float* __restrict__ g,
                    const float* __restrict__ b, __half* __restrict__ z16)
{
    const int row = blockIdx.x;
    const int tid = threadIdx.x;
    const float* p = z + (size_t)row * D_;
    float4 v = ((const float4*)p)[tid];
    float s  = v.x + v.y + v.z + v.w;
    float ss = v.x*v.x + v.y*v.y + v.z*v.z + v.w*v.w;
    #pragma unroll
    for (int o = 16; o; o >>= 1) {
        s  += __shfl_xor_sync(0xffffffffu, s,  o);
        ss += __shfl_xor_sync(0xffffffffu, ss, o);
    }
    __shared__ float ws[8], wss[8];
    __shared__ float mu_s, inv_s;
    int lane = tid & 31, wid = tid >> 5;
    if (lane == 0) { ws[wid] = s; wss[wid] = ss; }
    __syncthreads();
    if (tid == 0) {
        float S = 0.f, SS = 0.f;
        #pragma unroll
        for (int i = 0; i < 8; i++) { S += ws[i]; SS += wss[i]; }
        float mu = S * (1.f / D_);
        float var = SS * (1.f / D_) - mu * mu;
        mu_s = mu;
        inv_s = rsqrtf(var + 1e-5f);
    }
    __syncthreads();
    float mu = mu_s, inv = inv_s;
    float4 gg = ((const float4*)g)[tid];
    float4 bb = ((const float4*)b)[tid];
    float y[4] = { (v.x-mu)*inv*gg.x + bb.x, (v.y-mu)*inv*gg.y + bb.y,
                   (v.z-mu)*inv*gg.z + bb.z, (v.w-mu)*inv*gg.w + bb.w };
    float o[4];
    o[0] = 0.5f*y[0]*(1.f + erff(y[0]*0.70710678118654752f));
    o[1] = 0.5f*y[1]*(1.f + erff(y[1]*0.70710678118654752f));
    o[2] = 0.5f*y[2]*(1.f + erff(y[2]*0.70710678118654752f));
    o[3] = 0.5f*y[3]*(1.f + erff(y[3]*0.70710678118654752f));
    __half2* ph = (__half2*)(z16 + (size_t)row * D_);
    ph[2*tid]   = __half2(__float2half_rn(o[0]), __float2half_rn(o[1]));
    ph[2*tid+1] = __half2(__float2half_rn(o[2]), __float2half_rn(o[3]));
}

// =====================================================================
// Flash attention: one kernel per (m-tile 128, bh). smem: Q,K,V^T,P.
// =====================================================================
__global__ __launch_bounds__(256)
void attn_flash_kernel(const __half* __restrict__ q16, const __half* __restrict__ k16,
                       const __half* __restrict__ v16, __half* __restrict__ cx16)
{
    extern __shared__ __align__(16) char fsm[];
    const uint32_t base = smem_u32(fsm);
    float* pmax = (float*)(fsm + FRED_OFF);          // [4][128]
    float* psum = (float*)(fsm + FRED_OFF + 2048);   // [4][128]
    const int bh = blockIdx.y;
    const int b = bh >> 4, h = bh & 15;
    const int bm = blockIdx.x * 128;
    const int tid = threadIdx.x;
    const int wid = tid >> 5, lane = tid & 31;
    const int wm = wid & 1, wn = wid >> 1;

    #pragma unroll
    for (int it = 0; it < 4; it++) {
        int g = tid + it*256;
        int row = g >> 3, cc = g & 7;
        CP16(base + FQ_OFF + row*RB64 + cc*16,
             q16 + (size_t)(b*T_ + bm + row)*D_ + h*DH + cc*8, 16);
    }
    #pragma unroll
    for (int it = 0; it < 8; it++) {
        int g = tid + it*256;
        int row = g >> 3, cc = g & 7;
        CP16(base + FK_OFF + row*RB64 + cc*16,
             k16 + (size_t)(b*T_ + row)*D_ + h*DH + cc*8, 16);
    }
    CP_COMMIT();
    #pragma unroll
    for (int it = 0; it < 64; it++) {
        int g = tid + it*256;
        int t = g >> 6, d = g & 63;
        *(__half*)(fsm + FV_OFF + d*528 + t*2) =
            v16[(size_t)(b*T_ + t)*D_ + h*DH + d];
    }
    CP_WAIT0();
    __syncthreads();

    float acc[4][8][4] = {};
    #pragma unroll
    for (int kk = 0; kk < 64; kk += 16) {
        uint32_t bf[8][2];
        #pragma unroll
        for (int j = 0; j < 8; j++) {
            int nrow = wn*64 + j*8 + (lane & 7);
            int colb = (kk + ((lane >> 3) & 1)*8) * 2;
            LDMX2(bf[j], base + FK_OFF + nrow*RB64 + colb);
        }
        #pragma unroll
        for (int i = 0; i < 4; i++) {
            int mrow = wm*64 + i*16 + (lane & 15);
            int colb = (kk + ((lane >> 4) & 1)*8) * 2;
            uint32_t af[4];
            LDMX4(af, base + FQ_OFF + mrow*RB64 + colb);
            #pragma unroll
            for (int j = 0; j < 8; j++)
                MMA16816F(acc[i][j], af, bf[j]);
        }
    }
    #pragma unroll
    for (int i = 0; i < 4; i++)
        #pragma unroll
        for (int j = 0; j < 8; j++)
            #pragma unroll
            for (int q = 0; q < 4; q++)
                acc[i][j][q] *= 0.125f;

    #pragma unroll
    for (int i = 0; i < 4; i++) {
        float m0 = -1e30f, m1 = -1e30f;
        #pragma unroll
        for (int j = 0; j < 8; j++) {
            m0 = fmaxf(m0, fmaxf(acc[i][j][0], acc[i][j][1]));
            m1 = fmaxf(m1, fmaxf(acc[i][j][2], acc[i][j][3]));
        }
        #pragma unroll
        for (int o = 1; o < 4; o <<= 1) {
            m0 = fmaxf(m0, __shfl_xor_sync(0xffffffffu, m0, o));
            m1 = fmaxf(m1, __shfl_xor_sync(0xffffffffu, m1, o));
        }
        if ((lane & 3) == 0) {
            int r = wm*64 + i*16 + (lane >> 2);
            pmax[wn*128 + r]     = m0;
            pmax[wn*128 + r + 8] = m1;
        }
    }
    __syncthreads();
    #pragma unroll
    for (int i = 0; i < 4; i++) {
        int r0 = wm*64 + i*16 + (lane >> 2);
        float rm0 = fmaxf(fmaxf(pmax[r0], pmax[128+r0]),
                          fmaxf(pmax[256+r0], pmax[384+r0]));
        float rm1 = fmaxf(fmaxf(pmax[r0+8], pmax[128+r0+8]),
                          fmaxf(pmax[256+r0+8], pmax[384+r0+8]));
        float s0 = 0.f, s1 = 0.f;
        #pragma unroll
        for (int j = 0; j < 8; j++) {
            int col = wn*64 + j*8 + (lane & 3)*2;
            float e0 = __expf(acc[i][j][0] - rm0);
            float e1 = __expf(acc[i][j][1] - rm0);
            float e2 = __expf(acc[i][j][2] - rm1);
            float e3 = __expf(acc[i][j][3] - rm1);
            s0 += e0 + e1; s1 += e2 + e3;
            *(__half2*)(fsm + FP_OFF + r0*528 + col*2) =
                __half2(__float2half_rn(e0), __float2half_rn(e1));
            *(__half2*)(fsm + FP_OFF + (r0+8)*528 + col*2) =
                __half2(__float2half_rn(e2), __float2half_rn(e3));
        }
        #pragma unroll
        for (int o = 1; o < 4; o <<= 1) {
            s0 += __shfl_xor_sync(0xffffffffu, s0, o);
            s1 += __shfl_xor_sync(0xffffffffu, s1, o);
        }
        if ((lane & 3) == 0) {
            int r = wm*64 + i*16 + (lane >> 2);
            psum[wn*128 + r]     = s0;
            psum[wn*128 + r + 8] = s1;
        }
    }
    __syncthreads();

    float acc2[4][2][4] = {};
    #pragma unroll
    for (int kk = 0; kk < 256; kk += 16) {
        uint32_t bf[2][2];
        #pragma unroll
        for (int j = 0; j < 2; j++) {
            int nrow = wn*16 + j*8 + (lane & 7);
            int colb = (kk + ((lane >> 3) & 1)*8) * 2;
            LDMX2(bf[j], base + FV_OFF + nrow*528 + colb);
        }
        #pragma unroll
        for (int i = 0; i < 4; i++) {
            int mrow = wm*64 + i*16 + (lane & 15);
            int colb = (kk + ((lane >> 4) & 1)*8) * 2;
            uint32_t af[4];
            LDMX4(af, base + FP_OFF + mrow*528 + colb);
            #pragma unroll
            for (int j = 0; j < 2; j++)
                MMA16816F(acc2[i][j], af, bf[j]);
        }
    }
    #pragma unroll
    for (int i = 0; i < 4; i++) {
        int r0 = wm*64 + i*16 + (lane >> 2);
        float inv0 = 1.f / (psum[r0] + psum[128+r0] + psum[256+r0] + psum[384+r0]);
        float inv1 = 1.f / (psum[r0+8] + psum[128+r0+8] + psum[256+r0+8] + psum[384+r0+8]);
        #pragma unroll
        for (int j = 0; j < 2; j++) {
            int n0 = wn*16 + j*8 + (lane & 3)*2;
            size_t o01 = (size_t)(b*T_ + bm + r0)*D_ + h*DH + n0;
            size_t o23 = (size_t)(b*T_ + bm + r0 + 8)*D_ + h*DH + n0;
            *(__half2*)&cx16[o01] = __half2(__float2half_rn(acc2[i][j][0]*inv0),
                                            __float2half_rn(acc2[i][j][1]*inv0));
            *(__half2*)&cx16[o23] = __half2(__float2half_rn(acc2[i][j][2]*inv1),
                                            __float2half_rn(acc2[i][j][3]*inv1));
        }
    }
}

// =====================================================================
// GAT pieces
// =====================================================================
__global__ __launch_bounds__(256)
void e12_kernel(const float* __restrict__ hg, const float* __restrict__ a1,
                const float* __restrict__ a2, float* __restrict__ e1,
                float* __restrict__ e2)
{
    int wid  = (blockIdx.x * blockDim.x + threadIdx.x) >> 5;
    int lane = threadIdx.x & 31;
    int n = wid >> 3, h = wid & 7;
    const float* row = hg + (size_t)n * D_ + h * GDH;
    float s1 = 0.f, s2 = 0.f;
    #pragma unroll
    for (int r = 0; r < 4; r++) {
        float x = row[lane + 32*r];
        s1 += x * a1[lane + 32*r];
        s2 += x * a2[lane + 32*r];
    }
    #pragma unroll
    for (int o = 16; o; o >>= 1) {
        s1 += __shfl_xor_sync(0xffffffffu, s1, o);
        s2 += __shfl_xor_sync(0xffffffffu, s2, o);
    }
    if (lane == 0) { e1[n*HGAT + h] = s1; e2[n*HGAT + h] = s2; }
}

__global__ __launch_bounds__(256)
void e2max_kernel(const float* __restrict__ e2, float* __restrict__ m2)
{
    int h = blockIdx.x, tid = threadIdx.x;
    float m = -1e30f;
    for (int n = tid; n < M_; n += 256) m = fmaxf(m, e2[n*HGAT + h]);
    __shared__ float sm[256];
    sm[tid] = m; __syncthreads();
    for (int s = 128; s > 0; s >>= 1) {
        if (tid < s) sm[tid] = fmaxf(sm[tid], sm[tid + s]);
        __syncthreads();
    }
    if (tid == 0) m2[h] = sm[0];
}

// GAT aggregation: K64 chunks, fp16 HMMA, on-the-fly alpha + fused epilogue.
__global__ __launch_bounds__(256)
void gat_hmma_kernel(const __half* __restrict__ hgT, const float* __restrict__ e1,
                     const float* __restrict__ e2, const float* __restrict__ m2,
                     const float* __restrict__ feat, float* __restrict__ out)
{
    extern __shared__ __align__(16) char gsm[];
    const uint32_t aU = smem_u32(gsm);               // alpha tile at offset 0
    float* s_e1  = (float*)(gsm + GRED_OFF);
    float* s_mr  = (float*)(gsm + GRED_OFF + 512);
    float* dpart = (float*)(gsm + GRED_OFF + 1024);
    const int h  = blockIdx.x;
    const int bm = blockIdx.y * 128;
    const int tid = threadIdx.x;
    const int wid = tid >> 5, lane = tid & 31;
    const int wm = wid & 1, wn = wid >> 1;
    if (tid < 128) {
        float v1 = e1[(bm + tid)*HGAT + h];
        float sv = v1 + m2[h];
        s_mr[tid] = sv > 0.f ? sv : 0.2f * sv;
        s_e1[tid] = v1;
    }
    __syncthreads();
    const int am  = tid >> 1;                        // alpha row owned
    const int ak0 = (tid & 1) * 32;                  // half of the 64 k-cols
    const float e1v = s_e1[am], mrv = s_mr[am];
    float dreg = 0.f;
    float acc[4][4][4] = {};

#define ISSUE_B(c) do { \
    int k0 = (c) << 6; \
    uint32_t bufu = aU + GB_OFF + ((c) & 1) * TB64; \
    _Pragma("unroll") \
    for (int it = 0; it < 4; it++) { \
        int g = tid + it*256; \
        int row = g >> 3, cc = g & 7; \
        const __half* src = hgT + (size_t)(h*GDH + row)*M_ + k0 + cc*8; \
        CP16(bufu + row*RB64 + cc*16, src, 16); \
    } \
    CP_COMMIT(); } while (0)

    const int nc = M_ >> 6;               // 32
    ISSUE_B(0);
    for (int c = 0; c < nc; c++) {
        int k0 = c << 6;
        #pragma unroll
        for (int r = 0; r < 32; r++) {
            int j = k0 + ak0 + r;
            float ev = __ldg(&e2[j*HGAT + h]);
            float sv = e1v + ev;
            float lv = sv > 0.f ? sv : 0.2f * sv;
            __half a16 = __float2half_rn(__expf(lv - mrv));
            dreg += __half2float(a16);
            *(__half*)(gsm + am*RB64 + (ak0 + r)*2) = a16;
        }
        if (c + 1 < nc) { ISSUE_B(c + 1); CP_WAIT1(); }
        else            { CP_WAIT0(); }
        __syncthreads();
        uint32_t bU = aU + GB_OFF + (c & 1) * TB64;
        #pragma unroll
        for (int kk = 0; kk < 64; kk += 16) {
            uint32_t bhf[4][2];
            #pragma unroll
            for (int j = 0; j < 4; j++) {
                int nrow = wn*32 + j*8 + (lane & 7);
                int colb = (kk + ((lane >> 3) & 1)*8) * 2;
                LDMX2(bhf[j], bU + nrow*RB64 + colb);
            }
            #pragma unroll
            for (int i = 0; i < 4; i++) {
                int mrow = wm*64 + i*16 + (lane & 15);
                int colb = (kk + ((lane >> 4) & 1)*8) * 2;
                uint32_t ah[4];
                LDMX4(ah, aU + mrow*RB64 + colb);
                #pragma unroll
                for (int j = 0; j < 4; j++)
                    MMA16816F(acc[i][j], ah, bhf[j]);
            }
        }
        __syncthreads();
    }
#undef ISSUE_B
    dpart[tid] = dreg;
    __syncthreads();
    #pragma unroll
    for (int i = 0; i < 4; i++) {
        int ml = wm*64 + i*16 + (lane >> 2);
        int m0 = bm + ml;
        float inv0 = 1.f / (dpart[2*ml] + dpart[2*ml+1]);
        float inv1 = 1.f / (dpart[2*(ml+8)] + dpart[2*(ml+8)+1]);
        #pragma unroll
        for (int j = 0; j < 4; j++) {
            int n0 = wn*32 + j*8 + (lane & 3)*2;
            int col = h*GDH + n0;
            float v0 = acc[i][j][0]*inv0, v1 = acc[i][j][1]*inv0;
            float v2 = acc[i][j][2]*inv1, v3 = acc[i][j][3]*inv1;
            v0 = v0 > 0.f ? v0 : expm1f(v0);
            v1 = v1 > 0.f ? v1 : expm1f(v1);
            v2 = v2 > 0.f ? v2 : expm1f(v2);
            v3 = v3 > 0.f ? v3 : expm1f(v3);
            size_t o01 = (size_t)m0*D_ + col;
            size_t o23 = (size_t)(m0+8)*D_ + col;
            out[o01]   = v0 + feat[o01];
            out[o01+1] = v1 + feat[o01+1];
            out[o23]   = v2 + feat[o23];
            out[o23+1] = v3 + feat[o23+1];
        }
    }
}

// =====================================================================
extern "C" void kernel_launch(void* const* d_in, const int* in_sizes, int n_in,
                              void* d_out, int out_size)
{
    const float* feat = (const float*)d_in[0];

    Ptr5 cw{}, cb{};
    int wi = 0, bi = 0;
    for (int i = 1; i <= 10; i++) {
        if (in_sizes[i] == D_ * D_ * KW) { if (wi < 5) cw.p[wi++] = (const float*)d_in[i]; }
        else                             { if (bi < 5) cb.p[bi++] = (const float*)d_in[i]; }
    }

    const float* fp_w = (const float*)d_in[11];
    const float* fp_b = (const float*)d_in[12];
    const float* ln_g = (const float*)d_in[13];
    const float* ln_b = (const float*)d_in[14];
    const float* wq = (const float*)d_in[15];
    const float* bq = (const float*)d_in[16];
    const float* wk = (const float*)d_in[17];
    const float* bk = (const float*)d_in[18];
    const float* wv = (const float*)d_in[19];
    const float* bv = (const float*)d_in[20];
    const float* wo = (const float*)d_in[21];
    const float* bo = (const float*)d_in[22];
    const float* gat_w = (const float*)d_in[23];
    const float* gat_b = (const float*)d_in[24];
    const float* a1 = (const float*)d_in[25];
    const float* a2 = (const float*)d_in[26];
    float* out = (float*)d_out;

    __half *f16, *wt16, *fp16, *dw16, *ms16, *z16, *q16, *k16, *v16;
    __half *cx16, *at16, *hgT;
    float *z, *hg, *e1, *e2, *m2;
    cudaGetSymbolAddress((void**)&f16,  g_f16);
    cudaGetSymbolAddress((void**)&wt16, g_wt16);
    cudaGetSymbolAddress((void**)&fp16, g_fp16);
    cudaGetSymbolAddress((void**)&dw16, g_dw16);
    cudaGetSymbolAddress((void**)&ms16, g_ms16);
    cudaGetSymbolAddress((void**)&z,    g_z);
    cudaGetSymbolAddress((void**)&z16,  g_z16);
    cudaGetSymbolAddress((void**)&q16,  g_q16);
    cudaGetSymbolAddress((void**)&k16,  g_k16);
    cudaGetSymbolAddress((void**)&v16,  g_v16);
    cudaGetSymbolAddress((void**)&cx16, g_cx16);
    cudaGetSymbolAddress((void**)&at16, g_at16);
    cudaGetSymbolAddress((void**)&hg,   g_hg);
    cudaGetSymbolAddress((void**)&hgT,  g_hgT);
    cudaGetSymbolAddress((void**)&e1,   g_e1);
    cudaGetSymbolAddress((void**)&e2,   g_e2);
    cudaGetSymbolAddress((void**)&m2,   g_m2);

    cudaFuncSetAttribute(hmma_1t_f32,       cudaFuncAttributeMaxDynamicSharedMemorySize, SMEM_K64);
    cudaFuncSetAttribute(hmma_1t_f16,       cudaFuncAttributeMaxDynamicSharedMemorySize, SMEM_K64);
    cudaFuncSetAttribute(hmma_1t_qkv,       cudaFuncAttributeMaxDynamicSharedMemorySize, SMEM_K64);
    cudaFuncSetAttribute(hmma_conv_kernel,  cudaFuncAttributeMaxDynamicSharedMemorySize, SMEM_K64);
    cudaFuncSetAttribute(attn_flash_kernel, cudaFuncAttributeMaxDynamicSharedMemorySize, FSM_TOT);
    cudaFuncSetAttribute(gat_hmma_kernel,   cudaFuncAttributeMaxDynamicSharedMemorySize, GSM_TOT);

    // 0) conversions
    cvt_f16_kernel<<<(M_*D_/4 + 255)/256, 256>>>(feat, f16, M_*D_/4);
    wtrans5_smem_kernel<<<dim3(D_, 5), 256>>>(cw, wt16);
    cvt_f16_kernel<<<(D_*K5D/4 + 255)/256, 256>>>(fp_w, fp16, D_*K5D/4);
    Ptr5 dws{{ wq, wk, wv, wo, gat_w }};
    cvt5_f16_kernel<<<dim3(D_*D_/4/256, 5), 256>>>(dws, dw16);

    // 1) dilated convs (fp16 1-term, M128/K64, occupancy 2) -> ms16
    hmma_conv_kernel<<<dim3(8, 16, 5), 256, SMEM_K64>>>(f16, wt16, cb, ms16);

    // 2) fusion projection (K=5120) -> z fp32, then LN+GELU -> z16
    hmma_1t_f32<<<dim3(8, 16), 256, SMEM_K64>>>(ms16, fp16, fp_b, z, K5D, D_);
    ln_gelu_kernel<<<M_, 256>>>(z, ln_g, ln_b, z16);

    // 3) q, k, v projections (merged)
    QkvArgs qkv{{ q16, k16, v16 }, { bq, bk, bv }};
    hmma_1t_qkv<<<dim3(8, 16, 3), 256, SMEM_K64>>>(z16, dw16, qkv);

    // 4) attention: single flash kernel
    attn_flash_kernel<<<dim3(2, B_*HMHA), 256, FSM_TOT>>>(q16, k16, v16, cx16);

    // 5) wo -> at16; gat_w -> hg fp32
    hmma_1t_f16<<<dim3(8, 16), 256, SMEM_K64>>>(cx16,
        dw16 + 3*(size_t)D_*D_, bo, at16, D_, D_);
    hmma_1t_f32<<<dim3(8, 16), 256, SMEM_K64>>>(at16,
        dw16 + 4*(size_t)D_*D_, gat_b, hg, D_, D_);

    // 6) GAT logits, max, transpose
    e12_kernel<<<(M_*HGAT)/8, 256>>>(hg, a1, a2, e1, e2);
    e2max_kernel<<<HGAT, 256>>>(e2, m2);
    transpose_f16_kernel<<<dim3(M_/32, D_/32), 256>>>(hg, hgT);

    // 7) GAT aggregation (fp16 HMMA, K64) + ELU + residual -> d_out
    gat_hmma_kernel<<<dim3(HGAT, 16), 256, GSM_TOT>>>(hgT, e1, e2, m2, feat, out);
}